// round 15
// baseline (speedup 1.0000x reference)
#include <cuda_runtime.h>
#include <cuda_bf16.h>
#include <cstdint>
#include <math.h>

// ---------------------------------------------------------------------------
// B=8, L=1024, D=1024, H=16, d=64.  M = 8192 token rows.
// bf16 mma.sync + ldmatrix + cp.async.  GEMM: K-chunks of 64, 3-stage ring,
// single barrier per chunk.  Attention: 8m x 2n warps, P in registers.
// ---------------------------------------------------------------------------

#define M_ROWS  8192
#define DIM     1024
#define NCHUNK  128
#define CHUNK_ELEMS 65536

typedef __nv_bfloat16 bf16;

__device__ bf16 g_inb[3][M_ROWS * DIM];
__device__ bf16 g_wb[4][DIM * DIM];
__device__ bf16 g_pq[M_ROWS * DIM];
__device__ bf16 g_pk[M_ROWS * DIM];
__device__ bf16 g_pv[M_ROWS * DIM];
__device__ bf16 g_ctxb[M_ROWS * DIM];
__device__ float g_proj[M_ROWS * DIM];

__device__ __forceinline__ uint32_t smem_u32(const void* p) {
    uint32_t a;
    asm("{ .reg .u64 t; cvta.to.shared.u64 t, %1; cvt.u32.u64 %0, t; }"
        : "=r"(a) : "l"(p));
    return a;
}
__device__ __forceinline__ uint32_t packbf(float a, float b) {
    __nv_bfloat162 t = __floats2bfloat162_rn(a, b);
    return *reinterpret_cast<uint32_t*>(&t);
}
__device__ __forceinline__ void mma_bf16(float* c, const uint32_t* a,
                                         const uint32_t* b) {
    asm volatile(
        "mma.sync.aligned.m16n8k16.row.col.f32.bf16.bf16.f32 "
        "{%0,%1,%2,%3}, {%4,%5,%6,%7}, {%8,%9}, {%0,%1,%2,%3};"
        : "+f"(c[0]), "+f"(c[1]), "+f"(c[2]), "+f"(c[3])
        : "r"(a[0]), "r"(a[1]), "r"(a[2]), "r"(a[3]), "r"(b[0]), "r"(b[1]));
}
#define LDM_X4(r0, r1, r2, r3, addr) \
    asm volatile("ldmatrix.sync.aligned.m8n8.x4.shared.b16 {%0,%1,%2,%3}, [%4];" \
        : "=r"(r0), "=r"(r1), "=r"(r2), "=r"(r3) : "r"(addr))
#define LDM_X4T(r0, r1, r2, r3, addr) \
    asm volatile("ldmatrix.sync.aligned.m8n8.x4.trans.shared.b16 {%0,%1,%2,%3}, [%4];" \
        : "=r"(r0), "=r"(r1), "=r"(r2), "=r"(r3) : "r"(addr))
#define CP16(dst, src) \
    asm volatile("cp.async.cg.shared.global [%0], [%1], 16;" \
        :: "r"(dst), "l"(src) : "memory")
#define CP_COMMIT() asm volatile("cp.async.commit_group;" ::: "memory")
#define CP_WAIT(n)  asm volatile("cp.async.wait_group %0;" :: "n"(n) : "memory")

// Swizzled tile: 128 rows x 32 bf16 (2048 words).
__device__ __forceinline__ uint32_t swz(int m, int k) {
    return (uint32_t)(((m >> 1) << 5)
        + (((((m & 1) << 2) | (k >> 3)) ^ ((m >> 1) & 7)) << 2)
        + ((k >> 1) & 3));
}

// ---------------------------------------------------------------------------
// fp32 -> bf16 conversion (8 floats / thread)
// ---------------------------------------------------------------------------
struct CvtPtrs { const float* s[7]; bf16* d[7]; int n[7]; };

__global__ void __launch_bounds__(256) cvt_kernel(CvtPtrs cp)
{
    const int z = blockIdx.y;
    const int n = cp.n[z];
    const int idx = (blockIdx.x * 256 + threadIdx.x) * 8;
    if (idx >= n) return;
    float4 v0 = *(const float4*)(cp.s[z] + idx);
    float4 v1 = *(const float4*)(cp.s[z] + idx + 4);
    uint4 w = make_uint4(packbf(v0.x, v0.y), packbf(v0.z, v0.w),
                         packbf(v1.x, v1.y), packbf(v1.z, v1.w));
    *(uint4*)(cp.d[z] + idx) = w;
}

// ---------------------------------------------------------------------------
// bf16 GEMM: CTA 128x128, 256 thr, warps 2m x 4n, K chunks of 64 (4 k16),
// 3-stage cp.async ring, single barrier per chunk, 2 CTAs/SM.  z-batched.
// Stage (8192 words): A two 2048-word k32-subtiles | B same at +4096 words.
// ---------------------------------------------------------------------------
struct GemmPtrs {
    const bf16* A[3]; const bf16* W[3]; const float* bias[3];
    bf16* Cb[3]; float* Cf[3]; int write_f32;
};
#define G_STAGE_BYTES 32768
#define GEMM_SMEM_BYTES (3 * G_STAGE_BYTES)   // 98304

__global__ void __launch_bounds__(256, 2) gemm_bf16_cp(GemmPtrs gp)
{
    extern __shared__ __align__(16) uint32_t smg[];
    const uint32_t sb = smem_u32(smg);
    const int z = blockIdx.z;
    const bf16* A     = gp.A[z];
    const bf16* W     = gp.W[z];
    const float* bias = gp.bias[z];

    const int tid  = threadIdx.x;
    const int lane = tid & 31;
    const int wid  = tid >> 5;
    const int wm   = wid & 1;
    const int wn   = wid >> 1;
    const int row0 = blockIdx.y * 128;
    const int col0 = blockIdx.x * 128;

    // loader: thread -> row m, k-half h (32 bf16 = 4 octets), chunk stride 64
    const int m  = tid & 127;
    const int h  = tid >> 7;
    const bf16* Ap = A + (size_t)(row0 + m) * DIM + h * 32;
    const bf16* Wp = W + (size_t)(col0 + m) * DIM + h * 32;
    uint32_t dA[4], dB[4];
    #pragma unroll
    for (int j = 0; j < 4; j++) {
        dA[j] = sb + (h * 2048 + swz(m, j * 8)) * 4;
        dB[j] = dA[j] + 4096 * 4;
    }

    // ldmatrix lane geometry
    const int g = lane >> 3, li = lane & 7;
    const int aml = wm * 64 + (g & 1) * 8 + li;
    const int bnl = wn * 32 + ((g >> 1) & 1) * 8 + li;
    uint32_t aAddr[4], bAddr[4];
    #pragma unroll
    for (int ks = 0; ks < 4; ks++) {
        const int kla = ks * 16 + (g >> 1) * 8;
        const int klb = ks * 16 + (g & 1) * 8;
        aAddr[ks] = sb + ((kla >> 5) * 2048 + swz(aml, kla & 31)) * 4;
        bAddr[ks] = sb + (4096 + (klb >> 5) * 2048 + swz(bnl, klb & 31)) * 4;
    }

    float acc[4][4][4];
    #pragma unroll
    for (int mt = 0; mt < 4; mt++)
        #pragma unroll
        for (int nt = 0; nt < 4; nt++)
            #pragma unroll
            for (int f = 0; f < 4; f++) acc[mt][nt][f] = 0.0f;

    // prologue: stages 0,1
    #pragma unroll
    for (int s = 0; s < 2; s++) {
        const uint32_t so = (uint32_t)(s * G_STAGE_BYTES);
        const bf16* Ap2 = Ap + s * 64;
        const bf16* Wp2 = Wp + s * 64;
        #pragma unroll
        for (int j = 0; j < 4; j++) {
            CP16(dA[j] + so, Ap2 + j * 8);
            CP16(dB[j] + so, Wp2 + j * 8);
        }
        CP_COMMIT();
    }

    for (int c = 0; c < 16; ++c) {
        CP_WAIT(1);
        __syncthreads();   // single barrier: orders prev body before new CP16
        const uint32_t off = (uint32_t)((c % 3) * G_STAGE_BYTES);

        if (c + 2 < 16) {  // issue stage c+2 into slot (c+2)%3 = (c-1)%3
            const uint32_t so = (uint32_t)(((c + 2) % 3) * G_STAGE_BYTES);
            const bf16* Ap2 = Ap + (c + 2) * 64;
            const bf16* Wp2 = Wp + (c + 2) * 64;
            #pragma unroll
            for (int j = 0; j < 4; j++) {
                CP16(dA[j] + so, Ap2 + j * 8);
                CP16(dB[j] + so, Wp2 + j * 8);
            }
        }
        CP_COMMIT();       // empty group in tail keeps counting uniform

        #pragma unroll
        for (int ks = 0; ks < 4; ks++) {
            uint32_t af[4][4], bfr[4][2];
            #pragma unroll
            for (int mt = 0; mt < 4; mt++)
                LDM_X4(af[mt][0], af[mt][1], af[mt][2], af[mt][3],
                       aAddr[ks] + off + mt * 1024);
            #pragma unroll
            for (int pr = 0; pr < 2; pr++) {
                uint32_t r0, r1, r2, r3;
                LDM_X4(r0, r1, r2, r3, bAddr[ks] + off + pr * 1024);
                bfr[pr * 2][0] = r0; bfr[pr * 2][1] = r1;
                bfr[pr * 2 + 1][0] = r2; bfr[pr * 2 + 1][1] = r3;
            }
            #pragma unroll
            for (int mt = 0; mt < 4; mt++)
                #pragma unroll
                for (int nt = 0; nt < 4; nt++)
                    mma_bf16(acc[mt][nt], af[mt], bfr[nt]);
        }
    }

    const int qr = lane >> 2;
    const int qc = (lane & 3) * 2;
    if (gp.write_f32) {
        float* C = gp.Cf[z];
        #pragma unroll
        for (int nt = 0; nt < 4; nt++) {
            const int cc = col0 + wn * 32 + nt * 8 + qc;
            const float b0 = bias[cc], b1 = bias[cc + 1];
            #pragma unroll
            for (int mt = 0; mt < 4; mt++) {
                const int rr = row0 + wm * 64 + mt * 16 + qr;
                *(float2*)(C + (size_t)rr * DIM + cc) =
                    make_float2(acc[mt][nt][0] + b0, acc[mt][nt][1] + b1);
                *(float2*)(C + (size_t)(rr + 8) * DIM + cc) =
                    make_float2(acc[mt][nt][2] + b0, acc[mt][nt][3] + b1);
            }
        }
    } else {
        bf16* C = gp.Cb[z];
        #pragma unroll
        for (int nt = 0; nt < 4; nt++) {
            const int cc = col0 + wn * 32 + nt * 8 + qc;
            const float b0 = bias[cc], b1 = bias[cc + 1];
            #pragma unroll
            for (int mt = 0; mt < 4; mt++) {
                const int rr = row0 + wm * 64 + mt * 16 + qr;
                *(uint32_t*)(C + (size_t)rr * DIM + cc) =
                    packbf(acc[mt][nt][0] + b0, acc[mt][nt][1] + b1);
                *(uint32_t*)(C + (size_t)(rr + 8) * DIM + cc) =
                    packbf(acc[mt][nt][2] + b0, acc[mt][nt][3] + b1);
            }
        }
    }
}

// ---------------------------------------------------------------------------
// Attention (unchanged, R14): 512 thr, warps 8m x 2n, P in registers,
// exp/PV interleaved, single barrier per kt, cross-wn O reduce at end.
// ---------------------------------------------------------------------------
#define AT_KS 4096
#define AT_VS 12288
#define AT_OB 20480
#define AT_KM 28672
#define AT_RS 28928
#define AT_WORDS 29056
#define AT_SMEM_BYTES (AT_WORDS * 4)   // 116224

__global__ void __launch_bounds__(512) attn_bf16_cp(
    const float* __restrict__ qmask, const float* __restrict__ kmask)
{
    extern __shared__ __align__(16) uint32_t smw[];
    const uint32_t sbb = smem_u32(smw);
    float* obuf   = (float*)(smw + AT_OB);
    float* kmr    = (float*)(smw + AT_KM);   // double-buffered [2][128]
    float* rowsum = (float*)(smw + AT_RS);

    const int tid  = threadIdx.x;
    const int lane = tid & 31;
    const int wid  = tid >> 5;
    const int wm   = wid & 7;
    const int wn   = wid >> 3;
    const int r    = blockIdx.x;
    const int qt   = blockIdx.y;

    const bf16* Qc = g_pq + (size_t)r * CHUNK_ELEMS + qt * 8192;
    const bf16* Kc = g_pk + (size_t)r * CHUNK_ELEMS;
    const bf16* Vc = g_pv + (size_t)r * CHUNK_ELEMS;
    const float* qmb = qmask + (r & 7) * 1024 + qt * 128;
    const float* kmb = kmask + (r & 7) * 1024;

    const int lm = tid & 127;
    const int lq = tid >> 7;
    const int lk = lq * 16;
    const uint32_t lw0 = ((lk >> 5) * 2048 + swz(lm, lk & 31)) * 4;
    const uint32_t lw1 = ((lk >> 5) * 2048 + swz(lm, (lk & 31) + 8)) * 4;

    CP16(sbb + lw0, Qc + lm * 64 + lk);
    CP16(sbb + lw1, Qc + lm * 64 + lk + 8);
    {
        const bf16* ks_ = Kc + lm * 64 + lk;
        const bf16* vs_ = Vc + lm * 64 + lk;
        CP16(sbb + AT_KS * 4 + lw0, ks_);
        CP16(sbb + AT_KS * 4 + lw1, ks_ + 8);
        CP16(sbb + AT_VS * 4 + lw0, vs_);
        CP16(sbb + AT_VS * 4 + lw1, vs_ + 8);
    }
    CP_COMMIT();
    if (tid < 128) {
        rowsum[tid] = 0.0f;
        kmr[tid] = kmb[tid];
    }

    const int qrow = wm * 16 + (lane >> 2);
    const float qm0 = qmb[qrow];
    const float qm1 = qmb[qrow + 8];

    const int g = lane >> 3, li = lane & 7;

    float oacc[8][4];
    #pragma unroll
    for (int nd = 0; nd < 8; nd++)
        #pragma unroll
        for (int f = 0; f < 4; f++) oacc[nd][f] = 0.0f;
    float rs0 = 0.0f, rs1 = 0.0f;

    for (int kt = 0; kt < 8; kt++) {
        CP_WAIT(0);
        __syncthreads();

        if (kt + 1 < 8) {
            const uint32_t so = (uint32_t)(((kt + 1) & 1) * 16384);
            const bf16* ks_ = Kc + (kt + 1) * 8192 + lm * 64 + lk;
            const bf16* vs_ = Vc + (kt + 1) * 8192 + lm * 64 + lk;
            CP16(sbb + AT_KS * 4 + so + lw0, ks_);
            CP16(sbb + AT_KS * 4 + so + lw1, ks_ + 8);
            CP16(sbb + AT_VS * 4 + so + lw0, vs_);
            CP16(sbb + AT_VS * 4 + so + lw1, vs_ + 8);
            CP_COMMIT();
            if (tid < 128)
                kmr[((kt + 1) & 1) * 128 + tid] = kmb[(kt + 1) * 128 + tid];
        }
        const float* kmc = kmr + (kt & 1) * 128;
        const uint32_t kvo = (uint32_t)((kt & 1) * 16384);

        float sacc[8][4];
        #pragma unroll
        for (int nt = 0; nt < 8; nt++)
            #pragma unroll
            for (int f = 0; f < 4; f++) sacc[nt][f] = 0.0f;

        #pragma unroll
        for (int ks = 0; ks < 4; ks++) {
            uint32_t af[4], bfr[8][2];
            {
                const int ml = wm * 16 + (g & 1) * 8 + li;
                const int kl = ks * 16 + (g >> 1) * 8;
                const uint32_t ad = sbb + ((kl >> 5) * 2048 + swz(ml, kl & 31)) * 4;
                LDM_X4(af[0], af[1], af[2], af[3], ad);
            }
            #pragma unroll
            for (int pr = 0; pr < 4; pr++) {
                const int nl = wn * 64 + pr * 16 + ((g >> 1) & 1) * 8 + li;
                const int kl = ks * 16 + (g & 1) * 8;
                const uint32_t ad = sbb + AT_KS * 4 + kvo
                                    + ((kl >> 5) * 2048 + swz(nl, kl & 31)) * 4;
                uint32_t r0, r1, r2, r3;
                LDM_X4(r0, r1, r2, r3, ad);
                bfr[pr * 2][0] = r0; bfr[pr * 2][1] = r1;
                bfr[pr * 2 + 1][0] = r2; bfr[pr * 2 + 1][1] = r3;
            }
            #pragma unroll
            for (int nt = 0; nt < 8; nt++)
                mma_bf16(sacc[nt], af, bfr[nt]);
        }

        #pragma unroll
        for (int j = 0; j < 4; j++) {
            uint32_t pa[4];
            #pragma unroll
            for (int half = 0; half < 2; half++) {
                const int nt = 2 * j + half;
                const float k0v = kmc[2 * (nt * 4 + (lane & 3)) + wn * 64];
                const float k1v = kmc[2 * (nt * 4 + (lane & 3)) + 1 + wn * 64];
                float p0 = (qm0 * k0v == 0.0f) ? 0.0f : __expf(sacc[nt][0] * 0.125f);
                float p1 = (qm0 * k1v == 0.0f) ? 0.0f : __expf(sacc[nt][1] * 0.125f);
                float p2 = (qm1 * k0v == 0.0f) ? 0.0f : __expf(sacc[nt][2] * 0.125f);
                float p3 = (qm1 * k1v == 0.0f) ? 0.0f : __expf(sacc[nt][3] * 0.125f);
                uint32_t w0 = packbf(p0, p1);
                uint32_t w1 = packbf(p2, p3);
                float2 f0 = __bfloat1622float2(*(__nv_bfloat162*)&w0);
                float2 f1 = __bfloat1622float2(*(__nv_bfloat162*)&w1);
                rs0 += f0.x + f0.y;
                rs1 += f1.x + f1.y;
                pa[half * 2]     = w0;
                pa[half * 2 + 1] = w1;
            }
            #pragma unroll
            for (int dd = 0; dd < 4; dd++) {
                const int rowl = wn * 64 + j * 16 + (g & 1) * 8 + li;
                const int dl   = dd * 16 + (g >> 1) * 8;
                const uint32_t ad = sbb + AT_VS * 4 + kvo
                                    + ((dl >> 5) * 2048 + swz(rowl, dl & 31)) * 4;
                uint32_t r0, r1, r2, r3;
                LDM_X4T(r0, r1, r2, r3, ad);
                uint32_t vb0[2] = { r0, r1 };
                uint32_t vb1[2] = { r2, r3 };
                mma_bf16(oacc[dd * 2],     pa, vb0);
                mma_bf16(oacc[dd * 2 + 1], pa, vb1);
            }
        }
    }

    {
        float v0 = rs0, v1 = rs1;
        v0 += __shfl_xor_sync(0xffffffffu, v0, 1);
        v0 += __shfl_xor_sync(0xffffffffu, v0, 2);
        v1 += __shfl_xor_sync(0xffffffffu, v1, 1);
        v1 += __shfl_xor_sync(0xffffffffu, v1, 2);
        if ((lane & 3) == 0) {
            atomicAdd(&rowsum[qrow], v0);
            atomicAdd(&rowsum[qrow + 8], v1);
        }
    }

    const int col0 = 2 * (lane & 3);
    if (wn == 0) {
        #pragma unroll
        for (int nd = 0; nd < 8; nd++) {
            const int col = nd * 8 + col0;
            *(float2*)&obuf[qrow * 64 + col] =
                make_float2(oacc[nd][0], oacc[nd][1]);
            *(float2*)&obuf[(qrow + 8) * 64 + col] =
                make_float2(oacc[nd][2], oacc[nd][3]);
        }
    }
    __syncthreads();
    if (wn == 1) {
        bf16* Oc = g_ctxb + (size_t)r * CHUNK_ELEMS + qt * 8192;
        const float inv0 = 1.0f / fmaxf(rowsum[qrow], 2e-15f);
        const float inv1 = 1.0f / fmaxf(rowsum[qrow + 8], 2e-15f);
        #pragma unroll
        for (int nd = 0; nd < 8; nd++) {
            const int col = nd * 8 + col0;
            float2 a0 = *(float2*)&obuf[qrow * 64 + col];
            float2 a1 = *(float2*)&obuf[(qrow + 8) * 64 + col];
            *(uint32_t*)(Oc + qrow * 64 + col) =
                packbf((oacc[nd][0] + a0.x) * inv0, (oacc[nd][1] + a0.y) * inv0);
            *(uint32_t*)(Oc + (qrow + 8) * 64 + col) =
                packbf((oacc[nd][2] + a1.x) * inv1, (oacc[nd][3] + a1.y) * inv1);
        }
    }
}

// ---------------------------------------------------------------------------
// Residual + LayerNorm (unchanged)
// ---------------------------------------------------------------------------
__global__ void __launch_bounds__(256) resid_ln_kernel(
    const float* __restrict__ resid, const float* __restrict__ gamma,
    const float* __restrict__ beta, float* __restrict__ out)
{
    __shared__ float red[8];
    __shared__ float bc;

    const int row = blockIdx.x;
    const int tid = threadIdx.x;
    const float* pr = g_proj + (size_t)row * 1024;
    const float* rr = resid + (size_t)row * 1024;

    float x[4];
    float sum = 0.0f;
    #pragma unroll
    for (int c = 0; c < 4; c++) {
        x[c] = rr[tid + 256 * c] + pr[tid + 256 * c];
        sum += x[c];
    }
    #pragma unroll
    for (int m = 16; m; m >>= 1) sum += __shfl_xor_sync(0xffffffffu, sum, m);
    if ((tid & 31) == 0) red[tid >> 5] = sum;
    __syncthreads();
    if (tid == 0) {
        float t = 0.0f;
        #pragma unroll
        for (int i = 0; i < 8; i++) t += red[i];
        bc = t;
    }
    __syncthreads();
    const float mean = bc * (1.0f / 1024.0f);

    float vs = 0.0f;
    #pragma unroll
    for (int c = 0; c < 4; c++) { float d = x[c] - mean; vs += d * d; }
    #pragma unroll
    for (int m = 16; m; m >>= 1) vs += __shfl_xor_sync(0xffffffffu, vs, m);
    __syncthreads();
    if ((tid & 31) == 0) red[tid >> 5] = vs;
    __syncthreads();
    if (tid == 0) {
        float t = 0.0f;
        #pragma unroll
        for (int i = 0; i < 8; i++) t += red[i];
        bc = t;
    }
    __syncthreads();
    const float var = bc * (1.0f / 1024.0f);
    const float inv = rsqrtf(var + 1e-5f);

    #pragma unroll
    for (int c = 0; c < 4; c++) {
        int idx = tid + 256 * c;
        out[(size_t)row * 1024 + idx] =
            (x[c] - mean) * inv * gamma[idx] + beta[idx];
    }
}

// ---------------------------------------------------------------------------
// Host launcher
// ---------------------------------------------------------------------------
extern "C" void kernel_launch(void* const* d_in, const int* in_sizes, int n_in,
                              void* d_out, int out_size)
{
    const float* query  = (const float*)d_in[0];
    const float* key    = (const float*)d_in[1];
    const float* value  = (const float*)d_in[2];
    const float* q_mask = (const float*)d_in[3];
    const float* k_mask = (const float*)d_in[4];
    const float* Wq     = (const float*)d_in[5];
    const float* bq     = (const float*)d_in[6];
    const float* Wk     = (const float*)d_in[7];
    const float* bk     = (const float*)d_in[8];
    const float* Wv     = (const float*)d_in[9];
    const float* bv     = (const float*)d_in[10];
    const float* Wo     = (const float*)d_in[11];
    const float* bo     = (const float*)d_in[12];
    const float* gamma  = (const float*)d_in[13];
    const float* beta   = (const float*)d_in[14];
    float* out = (float*)d_out;

    (void)in_sizes; (void)n_in; (void)out_size;

    cudaFuncSetAttribute(attn_bf16_cp,
                         cudaFuncAttributeMaxDynamicSharedMemorySize,
                         AT_SMEM_BYTES);
    cudaFuncSetAttribute(gemm_bf16_cp,
                         cudaFuncAttributeMaxDynamicSharedMemorySize,
                         GEMM_SMEM_BYTES);

    bf16 *inb0, *inb1, *inb2, *wb0, *wb1, *wb2, *wb3;
    bf16 *pq, *pk, *pv, *ctxb;
    float *proj;
    cudaGetSymbolAddress((void**)&inb0, g_inb);
    inb1 = inb0 + (size_t)M_ROWS * DIM;
    inb2 = inb1 + (size_t)M_ROWS * DIM;
    cudaGetSymbolAddress((void**)&wb0, g_wb);
    wb1 = wb0 + (size_t)DIM * DIM;
    wb2 = wb1 + (size_t)DIM * DIM;
    wb3 = wb2 + (size_t)DIM * DIM;
    cudaGetSymbolAddress((void**)&pq,   g_pq);
    cudaGetSymbolAddress((void**)&pk,   g_pk);
    cudaGetSymbolAddress((void**)&pv,   g_pv);
    cudaGetSymbolAddress((void**)&ctxb, g_ctxb);
    cudaGetSymbolAddress((void**)&proj, g_proj);

    CvtPtrs cv;
    cv.s[0] = query; cv.d[0] = inb0; cv.n[0] = M_ROWS * DIM;
    cv.s[1] = key;   cv.d[1] = inb1; cv.n[1] = M_ROWS * DIM;
    cv.s[2] = value; cv.d[2] = inb2; cv.n[2] = M_ROWS * DIM;
    cv.s[3] = Wq;    cv.d[3] = wb0;  cv.n[3] = DIM * DIM;
    cv.s[4] = Wk;    cv.d[4] = wb1;  cv.n[4] = DIM * DIM;
    cv.s[5] = Wv;    cv.d[5] = wb2;  cv.n[5] = DIM * DIM;
    cv.s[6] = Wo;    cv.d[6] = wb3;  cv.n[6] = DIM * DIM;
    cvt_kernel<<<dim3(M_ROWS * DIM / 2048, 7), 256>>>(cv);

    GemmPtrs g3;
    g3.A[0] = inb0; g3.W[0] = wb0; g3.bias[0] = bq; g3.Cb[0] = pq; g3.Cf[0] = nullptr;
    g3.A[1] = inb1; g3.W[1] = wb1; g3.bias[1] = bk; g3.Cb[1] = pk; g3.Cf[1] = nullptr;
    g3.A[2] = inb2; g3.W[2] = wb2; g3.bias[2] = bv; g3.Cb[2] = pv; g3.Cf[2] = nullptr;
    g3.write_f32 = 0;
    gemm_bf16_cp<<<dim3(8, 64, 3), 256, GEMM_SMEM_BYTES>>>(g3);

    attn_bf16_cp<<<dim3(NCHUNK, 8), 512, AT_SMEM_BYTES>>>(q_mask, k_mask);

    GemmPtrs g1;
    g1.A[0] = ctxb; g1.W[0] = wb3; g1.bias[0] = bo; g1.Cb[0] = nullptr; g1.Cf[0] = proj;
    g1.A[1] = ctxb; g1.W[1] = wb3; g1.bias[1] = bo; g1.Cb[1] = nullptr; g1.Cf[1] = proj;
    g1.A[2] = ctxb; g1.W[2] = wb3; g1.bias[2] = bo; g1.Cb[2] = nullptr; g1.Cf[2] = proj;
    g1.write_f32 = 1;
    gemm_bf16_cp<<<dim3(8, 64, 1), 256, GEMM_SMEM_BYTES>>>(g1);

    resid_ln_kernel<<<M_ROWS, 256>>>(query, gamma, beta, out);
}

// round 16
// speedup vs baseline: 1.0533x; 1.0533x over previous
#include <cuda_runtime.h>
#include <cuda_bf16.h>
#include <cstdint>
#include <math.h>

// ---------------------------------------------------------------------------
// B=8, L=1024, D=1024, H=16, d=64.  M = 8192 token rows.
// bf16 mma.sync + ldmatrix + cp.async.  GEMM: R14 config (K-chunk 32,
// 4-stage ring, single barrier).  Attention: 8m x 2n, P in registers.
// cvt: 8 floats/thread.
// ---------------------------------------------------------------------------

#define M_ROWS  8192
#define DIM     1024
#define NCHUNK  128
#define CHUNK_ELEMS 65536

typedef __nv_bfloat16 bf16;

__device__ bf16 g_inb[3][M_ROWS * DIM];
__device__ bf16 g_wb[4][DIM * DIM];
__device__ bf16 g_pq[M_ROWS * DIM];
__device__ bf16 g_pk[M_ROWS * DIM];
__device__ bf16 g_pv[M_ROWS * DIM];
__device__ bf16 g_ctxb[M_ROWS * DIM];
__device__ float g_proj[M_ROWS * DIM];

__device__ __forceinline__ uint32_t smem_u32(const void* p) {
    uint32_t a;
    asm("{ .reg .u64 t; cvta.to.shared.u64 t, %1; cvt.u32.u64 %0, t; }"
        : "=r"(a) : "l"(p));
    return a;
}
__device__ __forceinline__ uint32_t packbf(float a, float b) {
    __nv_bfloat162 t = __floats2bfloat162_rn(a, b);
    return *reinterpret_cast<uint32_t*>(&t);
}
__device__ __forceinline__ void mma_bf16(float* c, const uint32_t* a,
                                         const uint32_t* b) {
    asm volatile(
        "mma.sync.aligned.m16n8k16.row.col.f32.bf16.bf16.f32 "
        "{%0,%1,%2,%3}, {%4,%5,%6,%7}, {%8,%9}, {%0,%1,%2,%3};"
        : "+f"(c[0]), "+f"(c[1]), "+f"(c[2]), "+f"(c[3])
        : "r"(a[0]), "r"(a[1]), "r"(a[2]), "r"(a[3]), "r"(b[0]), "r"(b[1]));
}
#define LDM_X4(r0, r1, r2, r3, addr) \
    asm volatile("ldmatrix.sync.aligned.m8n8.x4.shared.b16 {%0,%1,%2,%3}, [%4];" \
        : "=r"(r0), "=r"(r1), "=r"(r2), "=r"(r3) : "r"(addr))
#define LDM_X4T(r0, r1, r2, r3, addr) \
    asm volatile("ldmatrix.sync.aligned.m8n8.x4.trans.shared.b16 {%0,%1,%2,%3}, [%4];" \
        : "=r"(r0), "=r"(r1), "=r"(r2), "=r"(r3) : "r"(addr))
#define CP16(dst, src) \
    asm volatile("cp.async.cg.shared.global [%0], [%1], 16;" \
        :: "r"(dst), "l"(src) : "memory")
#define CP_COMMIT() asm volatile("cp.async.commit_group;" ::: "memory")
#define CP_WAIT(n)  asm volatile("cp.async.wait_group %0;" :: "n"(n) : "memory")

// Swizzled tile: 128 rows x 32 bf16 (2048 words).
__device__ __forceinline__ uint32_t swz(int m, int k) {
    return (uint32_t)(((m >> 1) << 5)
        + (((((m & 1) << 2) | (k >> 3)) ^ ((m >> 1) & 7)) << 2)
        + ((k >> 1) & 3));
}

// ---------------------------------------------------------------------------
// fp32 -> bf16 conversion (8 floats / thread)
// ---------------------------------------------------------------------------
struct CvtPtrs { const float* s[7]; bf16* d[7]; int n[7]; };

__global__ void __launch_bounds__(256) cvt_kernel(CvtPtrs cp)
{
    const int z = blockIdx.y;
    const int n = cp.n[z];
    const int idx = (blockIdx.x * 256 + threadIdx.x) * 8;
    if (idx >= n) return;
    float4 v0 = *(const float4*)(cp.s[z] + idx);
    float4 v1 = *(const float4*)(cp.s[z] + idx + 4);
    uint4 w = make_uint4(packbf(v0.x, v0.y), packbf(v0.z, v0.w),
                         packbf(v1.x, v1.y), packbf(v1.z, v1.w));
    *(uint4*)(cp.d[z] + idx) = w;
}

// ---------------------------------------------------------------------------
// bf16 GEMM (R14 config): CTA 128x128, 256 thr, warps 2m x 4n, K chunks of
// 32, 4-stage cp.async ring, ONE barrier per chunk, 2 CTAs/SM.  z-batched.
// ---------------------------------------------------------------------------
struct GemmPtrs {
    const bf16* A[3]; const bf16* W[3]; const float* bias[3];
    bf16* Cb[3]; float* Cf[3]; int write_f32;
};
#define G_STAGE_BYTES 16384
#define GEMM_SMEM_BYTES (4 * G_STAGE_BYTES)   // 65536

__global__ void __launch_bounds__(256, 2) gemm_bf16_cp(GemmPtrs gp)
{
    extern __shared__ __align__(16) uint32_t smg[];
    const uint32_t sb = smem_u32(smg);
    const int z = blockIdx.z;
    const bf16* A     = gp.A[z];
    const bf16* W     = gp.W[z];
    const float* bias = gp.bias[z];

    const int tid  = threadIdx.x;
    const int lane = tid & 31;
    const int wid  = tid >> 5;
    const int wm   = wid & 1;
    const int wn   = wid >> 1;
    const int row0 = blockIdx.y * 128;
    const int col0 = blockIdx.x * 128;

    const int m  = tid & 127;
    const int h  = tid >> 7;
    const int k0 = h * 16;
    const bf16* Ap = A + (size_t)(row0 + m) * DIM + k0;
    const bf16* Wp = W + (size_t)(col0 + m) * DIM + k0;
    const uint32_t dA0 = sb + swz(m, k0) * 4;
    const uint32_t dA1 = sb + swz(m, k0 + 8) * 4;
    const uint32_t dB0 = sb + (2048 + swz(m, k0)) * 4;
    const uint32_t dB1 = sb + (2048 + swz(m, k0 + 8)) * 4;

    const int g = lane >> 3, li = lane & 7;
    const int aml = wm * 64 + (g & 1) * 8 + li;
    const int bnl = wn * 32 + ((g >> 1) & 1) * 8 + li;
    uint32_t aAddr[2], bAddr[2];
    #pragma unroll
    for (int ks = 0; ks < 2; ks++) {
        aAddr[ks] = sb + swz(aml, ks * 16 + (g >> 1) * 8) * 4;
        bAddr[ks] = sb + (2048 + swz(bnl, ks * 16 + (g & 1) * 8)) * 4;
    }

    float acc[4][4][4];
    #pragma unroll
    for (int mt = 0; mt < 4; mt++)
        #pragma unroll
        for (int nt = 0; nt < 4; nt++)
            #pragma unroll
            for (int f = 0; f < 4; f++) acc[mt][nt][f] = 0.0f;

    #pragma unroll
    for (int s = 0; s < 3; s++) {
        const uint32_t so = (uint32_t)(s * G_STAGE_BYTES);
        const bf16* Ap2 = Ap + s * 32;
        const bf16* Wp2 = Wp + s * 32;
        CP16(dA0 + so, Ap2);     CP16(dA1 + so, Ap2 + 8);
        CP16(dB0 + so, Wp2);     CP16(dB1 + so, Wp2 + 8);
        CP_COMMIT();
    }

    for (int c = 0; c < 32; ++c) {
        CP_WAIT(2);
        __syncthreads();   // single barrier: orders prev compute before new CP16
        const uint32_t off = (uint32_t)((c & 3) * G_STAGE_BYTES);

        if (c + 3 < 32) {  // issue stage c+3 into slot (c-1)&3 (readers done)
            const uint32_t so = (uint32_t)(((c + 3) & 3) * G_STAGE_BYTES);
            const bf16* Ap2 = Ap + (c + 3) * 32;
            const bf16* Wp2 = Wp + (c + 3) * 32;
            CP16(dA0 + so, Ap2);     CP16(dA1 + so, Ap2 + 8);
            CP16(dB0 + so, Wp2);     CP16(dB1 + so, Wp2 + 8);
        }
        CP_COMMIT();       // empty group in tail keeps counting uniform

        #pragma unroll
        for (int ks = 0; ks < 2; ks++) {
            uint32_t af[4][4], bfr[4][2];
            #pragma unroll
            for (int mt = 0; mt < 4; mt++)
                LDM_X4(af[mt][0], af[mt][1], af[mt][2], af[mt][3],
                       aAddr[ks] + off + mt * 1024);
            #pragma unroll
            for (int pr = 0; pr < 2; pr++) {
                uint32_t r0, r1, r2, r3;
                LDM_X4(r0, r1, r2, r3, bAddr[ks] + off + pr * 1024);
                bfr[pr * 2][0] = r0; bfr[pr * 2][1] = r1;
                bfr[pr * 2 + 1][0] = r2; bfr[pr * 2 + 1][1] = r3;
            }
            #pragma unroll
            for (int mt = 0; mt < 4; mt++)
                #pragma unroll
                for (int nt = 0; nt < 4; nt++)
                    mma_bf16(acc[mt][nt], af[mt], bfr[nt]);
        }
    }

    const int qr = lane >> 2;
    const int qc = (lane & 3) * 2;
    if (gp.write_f32) {
        float* C = gp.Cf[z];
        #pragma unroll
        for (int nt = 0; nt < 4; nt++) {
            const int cc = col0 + wn * 32 + nt * 8 + qc;
            const float b0 = bias[cc], b1 = bias[cc + 1];
            #pragma unroll
            for (int mt = 0; mt < 4; mt++) {
                const int rr = row0 + wm * 64 + mt * 16 + qr;
                *(float2*)(C + (size_t)rr * DIM + cc) =
                    make_float2(acc[mt][nt][0] + b0, acc[mt][nt][1] + b1);
                *(float2*)(C + (size_t)(rr + 8) * DIM + cc) =
                    make_float2(acc[mt][nt][2] + b0, acc[mt][nt][3] + b1);
            }
        }
    } else {
        bf16* C = gp.Cb[z];
        #pragma unroll
        for (int nt = 0; nt < 4; nt++) {
            const int cc = col0 + wn * 32 + nt * 8 + qc;
            const float b0 = bias[cc], b1 = bias[cc + 1];
            #pragma unroll
            for (int mt = 0; mt < 4; mt++) {
                const int rr = row0 + wm * 64 + mt * 16 + qr;
                *(uint32_t*)(C + (size_t)rr * DIM + cc) =
                    packbf(acc[mt][nt][0] + b0, acc[mt][nt][1] + b1);
                *(uint32_t*)(C + (size_t)(rr + 8) * DIM + cc) =
                    packbf(acc[mt][nt][2] + b0, acc[mt][nt][3] + b1);
            }
        }
    }
}

// ---------------------------------------------------------------------------
// Attention (R14): 512 thr, warps 8m x 2n, P in registers, exp/PV
// interleaved, single barrier per kt, cross-wn O reduce at end.
// ---------------------------------------------------------------------------
#define AT_KS 4096
#define AT_VS 12288
#define AT_OB 20480
#define AT_KM 28672
#define AT_RS 28928
#define AT_WORDS 29056
#define AT_SMEM_BYTES (AT_WORDS * 4)   // 116224

__global__ void __launch_bounds__(512) attn_bf16_cp(
    const float* __restrict__ qmask, const float* __restrict__ kmask)
{
    extern __shared__ __align__(16) uint32_t smw[];
    const uint32_t sbb = smem_u32(smw);
    float* obuf   = (float*)(smw + AT_OB);
    float* kmr    = (float*)(smw + AT_KM);   // double-buffered [2][128]
    float* rowsum = (float*)(smw + AT_RS);

    const int tid  = threadIdx.x;
    const int lane = tid & 31;
    const int wid  = tid >> 5;
    const int wm   = wid & 7;
    const int wn   = wid >> 3;
    const int r    = blockIdx.x;
    const int qt   = blockIdx.y;

    const bf16* Qc = g_pq + (size_t)r * CHUNK_ELEMS + qt * 8192;
    const bf16* Kc = g_pk + (size_t)r * CHUNK_ELEMS;
    const bf16* Vc = g_pv + (size_t)r * CHUNK_ELEMS;
    const float* qmb = qmask + (r & 7) * 1024 + qt * 128;
    const float* kmb = kmask + (r & 7) * 1024;

    const int lm = tid & 127;
    const int lq = tid >> 7;
    const int lk = lq * 16;
    const uint32_t lw0 = ((lk >> 5) * 2048 + swz(lm, lk & 31)) * 4;
    const uint32_t lw1 = ((lk >> 5) * 2048 + swz(lm, (lk & 31) + 8)) * 4;

    CP16(sbb + lw0, Qc + lm * 64 + lk);
    CP16(sbb + lw1, Qc + lm * 64 + lk + 8);
    {
        const bf16* ks_ = Kc + lm * 64 + lk;
        const bf16* vs_ = Vc + lm * 64 + lk;
        CP16(sbb + AT_KS * 4 + lw0, ks_);
        CP16(sbb + AT_KS * 4 + lw1, ks_ + 8);
        CP16(sbb + AT_VS * 4 + lw0, vs_);
        CP16(sbb + AT_VS * 4 + lw1, vs_ + 8);
    }
    CP_COMMIT();
    if (tid < 128) {
        rowsum[tid] = 0.0f;
        kmr[tid] = kmb[tid];
    }

    const int qrow = wm * 16 + (lane >> 2);
    const float qm0 = qmb[qrow];
    const float qm1 = qmb[qrow + 8];

    const int g = lane >> 3, li = lane & 7;

    float oacc[8][4];
    #pragma unroll
    for (int nd = 0; nd < 8; nd++)
        #pragma unroll
        for (int f = 0; f < 4; f++) oacc[nd][f] = 0.0f;
    float rs0 = 0.0f, rs1 = 0.0f;

    for (int kt = 0; kt < 8; kt++) {
        CP_WAIT(0);
        __syncthreads();

        if (kt + 1 < 8) {
            const uint32_t so = (uint32_t)(((kt + 1) & 1) * 16384);
            const bf16* ks_ = Kc + (kt + 1) * 8192 + lm * 64 + lk;
            const bf16* vs_ = Vc + (kt + 1) * 8192 + lm * 64 + lk;
            CP16(sbb + AT_KS * 4 + so + lw0, ks_);
            CP16(sbb + AT_KS * 4 + so + lw1, ks_ + 8);
            CP16(sbb + AT_VS * 4 + so + lw0, vs_);
            CP16(sbb + AT_VS * 4 + so + lw1, vs_ + 8);
            CP_COMMIT();
            if (tid < 128)
                kmr[((kt + 1) & 1) * 128 + tid] = kmb[(kt + 1) * 128 + tid];
        }
        const float* kmc = kmr + (kt & 1) * 128;
        const uint32_t kvo = (uint32_t)((kt & 1) * 16384);

        float sacc[8][4];
        #pragma unroll
        for (int nt = 0; nt < 8; nt++)
            #pragma unroll
            for (int f = 0; f < 4; f++) sacc[nt][f] = 0.0f;

        #pragma unroll
        for (int ks = 0; ks < 4; ks++) {
            uint32_t af[4], bfr[8][2];
            {
                const int ml = wm * 16 + (g & 1) * 8 + li;
                const int kl = ks * 16 + (g >> 1) * 8;
                const uint32_t ad = sbb + ((kl >> 5) * 2048 + swz(ml, kl & 31)) * 4;
                LDM_X4(af[0], af[1], af[2], af[3], ad);
            }
            #pragma unroll
            for (int pr = 0; pr < 4; pr++) {
                const int nl = wn * 64 + pr * 16 + ((g >> 1) & 1) * 8 + li;
                const int kl = ks * 16 + (g & 1) * 8;
                const uint32_t ad = sbb + AT_KS * 4 + kvo
                                    + ((kl >> 5) * 2048 + swz(nl, kl & 31)) * 4;
                uint32_t r0, r1, r2, r3;
                LDM_X4(r0, r1, r2, r3, ad);
                bfr[pr * 2][0] = r0; bfr[pr * 2][1] = r1;
                bfr[pr * 2 + 1][0] = r2; bfr[pr * 2 + 1][1] = r3;
            }
            #pragma unroll
            for (int nt = 0; nt < 8; nt++)
                mma_bf16(sacc[nt], af, bfr[nt]);
        }

        #pragma unroll
        for (int j = 0; j < 4; j++) {
            uint32_t pa[4];
            #pragma unroll
            for (int half = 0; half < 2; half++) {
                const int nt = 2 * j + half;
                const float k0v = kmc[2 * (nt * 4 + (lane & 3)) + wn * 64];
                const float k1v = kmc[2 * (nt * 4 + (lane & 3)) + 1 + wn * 64];
                float p0 = (qm0 * k0v == 0.0f) ? 0.0f : __expf(sacc[nt][0] * 0.125f);
                float p1 = (qm0 * k1v == 0.0f) ? 0.0f : __expf(sacc[nt][1] * 0.125f);
                float p2 = (qm1 * k0v == 0.0f) ? 0.0f : __expf(sacc[nt][2] * 0.125f);
                float p3 = (qm1 * k1v == 0.0f) ? 0.0f : __expf(sacc[nt][3] * 0.125f);
                uint32_t w0 = packbf(p0, p1);
                uint32_t w1 = packbf(p2, p3);
                float2 f0 = __bfloat1622float2(*(__nv_bfloat162*)&w0);
                float2 f1 = __bfloat1622float2(*(__nv_bfloat162*)&w1);
                rs0 += f0.x + f0.y;
                rs1 += f1.x + f1.y;
                pa[half * 2]     = w0;
                pa[half * 2 + 1] = w1;
            }
            #pragma unroll
            for (int dd = 0; dd < 4; dd++) {
                const int rowl = wn * 64 + j * 16 + (g & 1) * 8 + li;
                const int dl   = dd * 16 + (g >> 1) * 8;
                const uint32_t ad = sbb + AT_VS * 4 + kvo
                                    + ((dl >> 5) * 2048 + swz(rowl, dl & 31)) * 4;
                uint32_t r0, r1, r2, r3;
                LDM_X4T(r0, r1, r2, r3, ad);
                uint32_t vb0[2] = { r0, r1 };
                uint32_t vb1[2] = { r2, r3 };
                mma_bf16(oacc[dd * 2],     pa, vb0);
                mma_bf16(oacc[dd * 2 + 1], pa, vb1);
            }
        }
    }

    {
        float v0 = rs0, v1 = rs1;
        v0 += __shfl_xor_sync(0xffffffffu, v0, 1);
        v0 += __shfl_xor_sync(0xffffffffu, v0, 2);
        v1 += __shfl_xor_sync(0xffffffffu, v1, 1);
        v1 += __shfl_xor_sync(0xffffffffu, v1, 2);
        if ((lane & 3) == 0) {
            atomicAdd(&rowsum[qrow], v0);
            atomicAdd(&rowsum[qrow + 8], v1);
        }
    }

    const int col0 = 2 * (lane & 3);
    if (wn == 0) {
        #pragma unroll
        for (int nd = 0; nd < 8; nd++) {
            const int col = nd * 8 + col0;
            *(float2*)&obuf[qrow * 64 + col] =
                make_float2(oacc[nd][0], oacc[nd][1]);
            *(float2*)&obuf[(qrow + 8) * 64 + col] =
                make_float2(oacc[nd][2], oacc[nd][3]);
        }
    }
    __syncthreads();
    if (wn == 1) {
        bf16* Oc = g_ctxb + (size_t)r * CHUNK_ELEMS + qt * 8192;
        const float inv0 = 1.0f / fmaxf(rowsum[qrow], 2e-15f);
        const float inv1 = 1.0f / fmaxf(rowsum[qrow + 8], 2e-15f);
        #pragma unroll
        for (int nd = 0; nd < 8; nd++) {
            const int col = nd * 8 + col0;
            float2 a0 = *(float2*)&obuf[qrow * 64 + col];
            float2 a1 = *(float2*)&obuf[(qrow + 8) * 64 + col];
            *(uint32_t*)(Oc + qrow * 64 + col) =
                packbf((oacc[nd][0] + a0.x) * inv0, (oacc[nd][1] + a0.y) * inv0);
            *(uint32_t*)(Oc + (qrow + 8) * 64 + col) =
                packbf((oacc[nd][2] + a1.x) * inv1, (oacc[nd][3] + a1.y) * inv1);
        }
    }
}

// ---------------------------------------------------------------------------
// Residual + LayerNorm (unchanged)
// ---------------------------------------------------------------------------
__global__ void __launch_bounds__(256) resid_ln_kernel(
    const float* __restrict__ resid, const float* __restrict__ gamma,
    const float* __restrict__ beta, float* __restrict__ out)
{
    __shared__ float red[8];
    __shared__ float bc;

    const int row = blockIdx.x;
    const int tid = threadIdx.x;
    const float* pr = g_proj + (size_t)row * 1024;
    const float* rr = resid + (size_t)row * 1024;

    float x[4];
    float sum = 0.0f;
    #pragma unroll
    for (int c = 0; c < 4; c++) {
        x[c] = rr[tid + 256 * c] + pr[tid + 256 * c];
        sum += x[c];
    }
    #pragma unroll
    for (int m = 16; m; m >>= 1) sum += __shfl_xor_sync(0xffffffffu, sum, m);
    if ((tid & 31) == 0) red[tid >> 5] = sum;
    __syncthreads();
    if (tid == 0) {
        float t = 0.0f;
        #pragma unroll
        for (int i = 0; i < 8; i++) t += red[i];
        bc = t;
    }
    __syncthreads();
    const float mean = bc * (1.0f / 1024.0f);

    float vs = 0.0f;
    #pragma unroll
    for (int c = 0; c < 4; c++) { float d = x[c] - mean; vs += d * d; }
    #pragma unroll
    for (int m = 16; m; m >>= 1) vs += __shfl_xor_sync(0xffffffffu, vs, m);
    __syncthreads();
    if ((tid & 31) == 0) red[tid >> 5] = vs;
    __syncthreads();
    if (tid == 0) {
        float t = 0.0f;
        #pragma unroll
        for (int i = 0; i < 8; i++) t += red[i];
        bc = t;
    }
    __syncthreads();
    const float var = bc * (1.0f / 1024.0f);
    const float inv = rsqrtf(var + 1e-5f);

    #pragma unroll
    for (int c = 0; c < 4; c++) {
        int idx = tid + 256 * c;
        out[(size_t)row * 1024 + idx] =
            (x[c] - mean) * inv * gamma[idx] + beta[idx];
    }
}

// ---------------------------------------------------------------------------
// Host launcher
// ---------------------------------------------------------------------------
extern "C" void kernel_launch(void* const* d_in, const int* in_sizes, int n_in,
                              void* d_out, int out_size)
{
    const float* query  = (const float*)d_in[0];
    const float* key    = (const float*)d_in[1];
    const float* value  = (const float*)d_in[2];
    const float* q_mask = (const float*)d_in[3];
    const float* k_mask = (const float*)d_in[4];
    const float* Wq     = (const float*)d_in[5];
    const float* bq     = (const float*)d_in[6];
    const float* Wk     = (const float*)d_in[7];
    const float* bk     = (const float*)d_in[8];
    const float* Wv     = (const float*)d_in[9];
    const float* bv     = (const float*)d_in[10];
    const float* Wo     = (const float*)d_in[11];
    const float* bo     = (const float*)d_in[12];
    const float* gamma  = (const float*)d_in[13];
    const float* beta   = (const float*)d_in[14];
    float* out = (float*)d_out;

    (void)in_sizes; (void)n_in; (void)out_size;

    cudaFuncSetAttribute(attn_bf16_cp,
                         cudaFuncAttributeMaxDynamicSharedMemorySize,
                         AT_SMEM_BYTES);
    cudaFuncSetAttribute(gemm_bf16_cp,
                         cudaFuncAttributeMaxDynamicSharedMemorySize,
                         GEMM_SMEM_BYTES);

    bf16 *inb0, *inb1, *inb2, *wb0, *wb1, *wb2, *wb3;
    bf16 *pq, *pk, *pv, *ctxb;
    float *proj;
    cudaGetSymbolAddress((void**)&inb0, g_inb);
    inb1 = inb0 + (size_t)M_ROWS * DIM;
    inb2 = inb1 + (size_t)M_ROWS * DIM;
    cudaGetSymbolAddress((void**)&wb0, g_wb);
    wb1 = wb0 + (size_t)DIM * DIM;
    wb2 = wb1 + (size_t)DIM * DIM;
    wb3 = wb2 + (size_t)DIM * DIM;
    cudaGetSymbolAddress((void**)&pq,   g_pq);
    cudaGetSymbolAddress((void**)&pk,   g_pk);
    cudaGetSymbolAddress((void**)&pv,   g_pv);
    cudaGetSymbolAddress((void**)&ctxb, g_ctxb);
    cudaGetSymbolAddress((void**)&proj, g_proj);

    CvtPtrs cv;
    cv.s[0] = query; cv.d[0] = inb0; cv.n[0] = M_ROWS * DIM;
    cv.s[1] = key;   cv.d[1] = inb1; cv.n[1] = M_ROWS * DIM;
    cv.s[2] = value; cv.d[2] = inb2; cv.n[2] = M_ROWS * DIM;
    cv.s[3] = Wq;    cv.d[3] = wb0;  cv.n[3] = DIM * DIM;
    cv.s[4] = Wk;    cv.d[4] = wb1;  cv.n[4] = DIM * DIM;
    cv.s[5] = Wv;    cv.d[5] = wb2;  cv.n[5] = DIM * DIM;
    cv.s[6] = Wo;    cv.d[6] = wb3;  cv.n[6] = DIM * DIM;
    cvt_kernel<<<dim3(M_ROWS * DIM / 2048, 7), 256>>>(cv);

    GemmPtrs g3;
    g3.A[0] = inb0; g3.W[0] = wb0; g3.bias[0] = bq; g3.Cb[0] = pq; g3.Cf[0] = nullptr;
    g3.A[1] = inb1; g3.W[1] = wb1; g3.bias[1] = bk; g3.Cb[1] = pk; g3.Cf[1] = nullptr;
    g3.A[2] = inb2; g3.W[2] = wb2; g3.bias[2] = bv; g3.Cb[2] = pv; g3.Cf[2] = nullptr;
    g3.write_f32 = 0;
    gemm_bf16_cp<<<dim3(8, 64, 3), 256, GEMM_SMEM_BYTES>>>(g3);

    attn_bf16_cp<<<dim3(NCHUNK, 8), 512, AT_SMEM_BYTES>>>(q_mask, k_mask);

    GemmPtrs g1;
    g1.A[0] = ctxb; g1.W[0] = wb3; g1.bias[0] = bo; g1.Cb[0] = nullptr; g1.Cf[0] = proj;
    g1.A[1] = ctxb; g1.W[1] = wb3; g1.bias[1] = bo; g1.Cb[1] = nullptr; g1.Cf[1] = proj;
    g1.A[2] = ctxb; g1.W[2] = wb3; g1.bias[2] = bo; g1.Cb[2] = nullptr; g1.Cf[2] = proj;
    g1.write_f32 = 1;
    gemm_bf16_cp<<<dim3(8, 64, 1), 256, GEMM_SMEM_BYTES>>>(g1);

    resid_ln_kernel<<<M_ROWS, 256>>>(query, gamma, beta, out);
}